// round 3
// baseline (speedup 1.0000x reference)
#include <cuda_runtime.h>

// Problem constants
constexpr int NNODES = 100000;
constexpr int D      = 64;
constexpr int NE     = 1250000;
constexpr int SB     = (NNODES + 1023) / 1024;  // 98 scan blocks
constexpr int GEMM_BLOCKS = (NNODES + 127) / 128;  // 782
constexpr int HIST_BLOCKS = 1024;

// ---------------------------------------------------------------------------
// Device scratch
// ---------------------------------------------------------------------------
__device__ float  g_h[NNODES * D];
__device__ float  g_x[NNODES * D];
__device__ float  g_dis[NNODES];
__device__ int    g_cnt[NNODES];
__device__ int    g_rowptr[NNODES + 1];
__device__ int    g_cursor[NNODES];
__device__ int    g_colidx[NE];
__device__ int    g_blocksum[SB];
__device__ int    g_blockoff[SB];
__device__ double g_sum[D];
__device__ double g_sumsq[D];
__device__ float  g_scale[D];
__device__ float  g_shift[D];
__device__ int    g_is64;

// ---------------------------------------------------------------------------
// 0. init: zero counters/BN accums; block 0 also detects edge dtype
// ---------------------------------------------------------------------------
__global__ void k_init(const int* __restrict__ e) {
    int i = blockIdx.x * blockDim.x + threadIdx.x;
    if (i < NNODES) g_cnt[i] = 0;
    if (i < D) { g_sum[i] = 0.0; g_sumsq[i] = 0.0; }
    if (blockIdx.x == 0) {
        __shared__ int s_nz;
        if (threadIdx.x == 0) s_nz = 0;
        __syncthreads();
        int nz = 0;
        for (int j = threadIdx.x; j < 2048; j += blockDim.x)
            nz |= (e[2 * j + 1] != 0);
        if (nz) atomicOr(&s_nz, 1);
        __syncthreads();
        if (threadIdx.x == 0) g_is64 = (s_nz == 0) ? 1 : 0;
    }
}

// ---------------------------------------------------------------------------
// GEMM body (device fn): g_h[n] = [dis[n] *] (X[n] @ W^T)
// FFMA2 (f32x2) K-pair interleaved, swizzled conflict-free smem.
// ---------------------------------------------------------------------------
union U4 { float4 f; unsigned long long u[2]; };
union U2 { unsigned long long u; float2 f; };

template <bool SCALE>
__device__ __forceinline__ void gemm_body(const float* __restrict__ X,
                                          const float* __restrict__ W,
                                          int bid) {
    __shared__ float sx[128 * 64];  // row n: pair p at ((2p + 2n) & 63)
    __shared__ float sw[64 * 64];   // sw[kp*128 + g*16 + dl*2 + par] = W[g*8+dl][2kp+par]
    int tid = threadIdx.x;

    // stage W
    for (int i = tid; i < 4096; i += 256) {
        int d = i >> 6, k = i & 63;
        int kp = k >> 1, par = k & 1, g = d >> 3, dl = d & 7;
        sw[kp * 128 + g * 16 + dl * 2 + par] = W[i];
    }
    // stage X (swizzled)
    int n0 = bid * 128;
    const float4* X4 = (const float4*)X;
    for (int i = tid; i < 2048; i += 256) {
        int r = i >> 4, c = i & 15;  // local row, float4 col
        int n = n0 + r;
        float4 v = (n < NNODES) ? X4[(size_t)n * 16 + c]
                                : make_float4(0.f, 0.f, 0.f, 0.f);
        int p0 = 2 * c, p1 = 2 * c + 1;
        ((float2*)sx)[(r * 64 + ((2 * p0 + 2 * r) & 63)) >> 1] = make_float2(v.x, v.y);
        ((float2*)sx)[(r * 64 + ((2 * p1 + 2 * r) & 63)) >> 1] = make_float2(v.z, v.w);
    }
    __syncthreads();

    int tc = tid & 7, tr = tid >> 3;
    int nb = tr * 4;
    unsigned long long acc[4][8];
#pragma unroll
    for (int i = 0; i < 4; i++)
#pragma unroll
        for (int j = 0; j < 8; j++) acc[i][j] = 0ull;

#pragma unroll 4
    for (int kp = 0; kp < 32; kp++) {
        unsigned long long wv[8];
#pragma unroll
        for (int t = 0; t < 4; t++) {
            int q = (t + (tc >> 1)) & 3;  // bank-rotation
            U4 tmp;
            tmp.f = *(const float4*)&sw[kp * 128 + tc * 16 + q * 4];
            wv[2 * q] = tmp.u[0];
            wv[2 * q + 1] = tmp.u[1];
        }
        unsigned long long xv[4];
#pragma unroll
        for (int i = 0; i < 4; i++) {
            int n = nb + i;
            xv[i] = *(const unsigned long long*)&sx[n * 64 + ((2 * kp + 2 * n) & 63)];
        }
#pragma unroll
        for (int i = 0; i < 4; i++)
#pragma unroll
            for (int j = 0; j < 8; j++)
                asm("fma.rn.f32x2 %0, %1, %2, %0;"
                    : "+l"(acc[i][j]) : "l"(xv[i]), "l"(wv[j]));
    }

#pragma unroll
    for (int i = 0; i < 4; i++) {
        int n = n0 + nb + i;
        if (n < NNODES) {
            float dv = SCALE ? g_dis[n] : 1.0f;
            float o[8];
#pragma unroll
            for (int j = 0; j < 8; j++) {
                U2 p; p.u = acc[i][j];
                o[j] = (p.f.x + p.f.y) * dv;
            }
            *(float4*)&g_h[(size_t)n * 64 + tc * 8]     = make_float4(o[0], o[1], o[2], o[3]);
            *(float4*)&g_h[(size_t)n * 64 + tc * 8 + 4] = make_float4(o[4], o[5], o[6], o[7]);
        }
    }
}

__device__ __forceinline__ void hist_body(const void* __restrict__ ep, int hb) {
    int i0 = hb * 256 + threadIdx.x;
    int stride = HIST_BLOCKS * 256;
    if (g_is64) {
        const long long* e = (const long long*)ep;
        for (int i = i0; i < NE; i += stride)
            atomicAdd(&g_cnt[(int)e[NE + i]], 1);
    } else {
        const int* e = (const int*)ep;
        for (int i = i0; i < NE; i += stride)
            atomicAdd(&g_cnt[e[NE + i]], 1);
    }
}

// fused: layer-1 GEMM (no dis scaling) || dst histogram
__global__ void __launch_bounds__(256) k_fused1(const float* __restrict__ X,
                                                 const float* __restrict__ W,
                                                 const void* __restrict__ ep) {
    if (blockIdx.x < GEMM_BLOCKS) gemm_body<false>(X, W, blockIdx.x);
    else                          hist_body(ep, blockIdx.x - GEMM_BLOCKS);
}

__global__ void __launch_bounds__(256) k_gemm_s(const float* __restrict__ X,
                                                 const float* __restrict__ W) {
    gemm_body<true>(X ? X : g_x, W, blockIdx.x);
}

// ---------------------------------------------------------------------------
// Parallel scan (3 kernels)
// ---------------------------------------------------------------------------
__global__ void __launch_bounds__(256) k_scan1() {
    __shared__ int warpsum[8];
    int b = blockIdx.x, t = threadIdx.x;
    int base = b * 1024 + t * 4;
    int c[4]; int s = 0;
#pragma unroll
    for (int i = 0; i < 4; i++) {
        int idx = base + i;
        c[i] = (idx < NNODES) ? g_cnt[idx] : 0;
        s += c[i];
    }
    int lane = t & 31, w = t >> 5;
    int v = s;
#pragma unroll
    for (int off = 1; off < 32; off <<= 1) {
        int u = __shfl_up_sync(~0u, v, off);
        if (lane >= off) v += u;
    }
    if (lane == 31) warpsum[w] = v;
    __syncthreads();
    if (t < 8) {
        int u = warpsum[t];
#pragma unroll
        for (int off = 1; off < 8; off <<= 1) {
            int uu = __shfl_up_sync(0xffu, u, off);
            if (t >= off) u += uu;
        }
        warpsum[t] = u;
    }
    __syncthreads();
    int run = v - s + (w > 0 ? warpsum[w - 1] : 0);
#pragma unroll
    for (int i = 0; i < 4; i++) {
        int idx = base + i;
        if (idx < NNODES) g_rowptr[idx] = run;
        run += c[i];
    }
    if (t == 255) g_blocksum[b] = warpsum[7];
}

__global__ void __launch_bounds__(128) k_scan2() {
    __shared__ int sm[128];
    int t = threadIdx.x;
    int v = (t < SB) ? g_blocksum[t] : 0;
    sm[t] = v;
    __syncthreads();
    for (int off = 1; off < 128; off <<= 1) {
        int u = (t >= off) ? sm[t - off] : 0;
        __syncthreads();
        sm[t] += u;
        __syncthreads();
    }
    if (t < SB) g_blockoff[t] = sm[t] - v;
    if (t == SB - 1) g_rowptr[NNODES] = sm[t];
}

__global__ void __launch_bounds__(256) k_scan3() {
    int b = blockIdx.x, t = threadIdx.x;
    int off = g_blockoff[b];
    int base = b * 1024 + t * 4;
#pragma unroll
    for (int i = 0; i < 4; i++) {
        int idx = base + i;
        if (idx < NNODES) {
            int r = g_rowptr[idx] + off;
            g_rowptr[idx] = r;
            g_cursor[idx] = r;
            g_dis[idx] = rsqrtf((float)(g_cnt[idx] + 1));
        }
    }
}

// ---------------------------------------------------------------------------
// CSR fill
// ---------------------------------------------------------------------------
__global__ void k_fill(const void* __restrict__ ep) {
    int i0 = blockIdx.x * blockDim.x + threadIdx.x;
    int stride = gridDim.x * blockDim.x;
    if (g_is64) {
        const long long* e = (const long long*)ep;
        for (int i = i0; i < NE; i += stride) {
            int src = (int)e[i];
            int dst = (int)e[NE + i];
            int p = atomicAdd(&g_cursor[dst], 1);
            g_colidx[p] = src;
        }
    } else {
        const int* e = (const int*)ep;
        for (int i = i0; i < NE; i += stride) {
            int src = e[i];
            int dst = e[NE + i];
            int p = atomicAdd(&g_cursor[dst], 1);
            g_colidx[p] = src;
        }
    }
}

// ---------------------------------------------------------------------------
// Aggregation: warp per node. SRCSCALE: h is unscaled, apply dis[src]/dis[n].
// ---------------------------------------------------------------------------
template <bool SRCSCALE>
__global__ void __launch_bounds__(256) k_agg(const float* __restrict__ b) {
    int w = (blockIdx.x * blockDim.x + threadIdx.x) >> 5;
    int l = threadIdx.x & 31;
    if (w >= NNODES) return;
    const float2* __restrict__ h2 = (const float2*)g_h;
    float dvw = g_dis[w];
    float2 acc = h2[(size_t)w * 32 + l];
    if (SRCSCALE) { acc.x *= dvw; acc.y *= dvw; }
    int beg = g_rowptr[w];
    int end = g_rowptr[w + 1];
    int j = beg;
    for (; j + 3 < end; j += 4) {
        int s0 = g_colidx[j],     s1 = g_colidx[j + 1];
        int s2 = g_colidx[j + 2], s3 = g_colidx[j + 3];
        float2 a0 = h2[(size_t)s0 * 32 + l];
        float2 a1 = h2[(size_t)s1 * 32 + l];
        float2 a2 = h2[(size_t)s2 * 32 + l];
        float2 a3 = h2[(size_t)s3 * 32 + l];
        if (SRCSCALE) {
            float d0 = g_dis[s0], d1 = g_dis[s1], d2 = g_dis[s2], d3 = g_dis[s3];
            acc.x += a0.x * d0 + a1.x * d1 + a2.x * d2 + a3.x * d3;
            acc.y += a0.y * d0 + a1.y * d1 + a2.y * d2 + a3.y * d3;
        } else {
            acc.x += (a0.x + a1.x) + (a2.x + a3.x);
            acc.y += (a0.y + a1.y) + (a2.y + a3.y);
        }
    }
    for (; j < end; j++) {
        int s = g_colidx[j];
        float2 a = h2[(size_t)s * 32 + l];
        if (SRCSCALE) {
            float ds = g_dis[s];
            acc.x += a.x * ds; acc.y += a.y * ds;
        } else {
            acc.x += a.x; acc.y += a.y;
        }
    }
    float2 bv = ((const float2*)b)[l];
    float2 r;
    r.x = acc.x * dvw + bv.x;
    r.y = acc.y * dvw + bv.y;
    ((float2*)g_x)[(size_t)w * 32 + l] = r;
}

// ---------------------------------------------------------------------------
// BN column reduction (fp32 inner, double only at block reduce)
// ---------------------------------------------------------------------------
__global__ void __launch_bounds__(256) k_bnred() {
    int d  = threadIdx.x & 63;
    int r0 = blockIdx.x * 4 + (threadIdx.x >> 6);
    int rs = gridDim.x * 4;
    float s = 0.f, q = 0.f;
    for (int n = r0; n < NNODES; n += rs) {
        float v = g_x[(size_t)n * 64 + d];
        s += v;
        q += v * v;
    }
    __shared__ double ss[256], sq[256];
    ss[threadIdx.x] = (double)s;
    sq[threadIdx.x] = (double)q;
    __syncthreads();
    if (threadIdx.x < 64) {
        double sd = ss[threadIdx.x] + ss[threadIdx.x + 64] + ss[threadIdx.x + 128] + ss[threadIdx.x + 192];
        double qd = sq[threadIdx.x] + sq[threadIdx.x + 64] + sq[threadIdx.x + 128] + sq[threadIdx.x + 192];
        atomicAdd(&g_sum[d], sd);
        atomicAdd(&g_sumsq[d], qd);
    }
}

__global__ void k_bnprep(const float* __restrict__ gamma,
                         const float* __restrict__ beta) {
    int d = threadIdx.x;
    if (d >= D) return;
    double mean = g_sum[d] / (double)NNODES;
    double var  = g_sumsq[d] / (double)NNODES - mean * mean;
    double inv  = 1.0 / sqrt(var + 1e-5);
    double sc   = (double)gamma[d] * inv;
    g_scale[d] = (float)sc;
    g_shift[d] = (float)((double)beta[d] - mean * sc);
}

__global__ void __launch_bounds__(256) k_fin(float* __restrict__ out) {
    int i = blockIdx.x * blockDim.x + threadIdx.x;
    if (i >= NNODES * 16) return;
    float4 v = ((const float4*)g_x)[i];
    int d = (i & 15) * 4;
    v.x = v.x * g_scale[d + 0] + g_shift[d + 0];
    v.y = v.y * g_scale[d + 1] + g_shift[d + 1];
    v.z = v.z * g_scale[d + 2] + g_shift[d + 2];
    v.w = v.w * g_scale[d + 3] + g_shift[d + 3];
    ((float4*)out)[i] = v;
}

// ---------------------------------------------------------------------------
// Launch
// ---------------------------------------------------------------------------
extern "C" void kernel_launch(void* const* d_in, const int* in_sizes, int n_in,
                              void* d_out, int out_size) {
    const float* x     = (const float*)d_in[0];
    const void*  ei    = d_in[1];
    const float* Ws    = (const float*)d_in[2];
    const float* bs    = (const float*)d_in[3];
    const float* gamma = (const float*)d_in[4];
    const float* beta  = (const float*)d_in[5];
    float* out = (float*)d_out;

    int agg_blocks = (NNODES * 32 + 255) / 256;

    k_init<<<(NNODES + 255) / 256, 256>>>((const int*)ei);
    // layer-1 GEMM (unscaled) overlapped with dst histogram
    k_fused1<<<GEMM_BLOCKS + HIST_BLOCKS, 256>>>(x, Ws, ei);
    k_scan1<<<SB, 256>>>();
    k_scan2<<<1, 128>>>();
    k_scan3<<<SB, 256>>>();
    k_fill<<<2048, 256>>>(ei);

    k_agg<true><<<agg_blocks, 256>>>(bs);  // layer 1: apply dis per edge

    k_gemm_s<<<GEMM_BLOCKS, 256>>>(nullptr, Ws + 1 * 64 * 64);
    k_agg<false><<<agg_blocks, 256>>>(bs + 1 * 64);

    k_gemm_s<<<GEMM_BLOCKS, 256>>>(nullptr, Ws + 2 * 64 * 64);
    k_agg<false><<<agg_blocks, 256>>>(bs + 2 * 64);

    k_bnred<<<512, 256>>>();
    k_bnprep<<<1, 64>>>(gamma, beta);
    k_fin<<<(NNODES * 16 + 255) / 256, 256>>>(out);
}

// round 4
// speedup vs baseline: 2.8118x; 2.8118x over previous
#include <cuda_runtime.h>

// Problem constants
constexpr int NNODES = 100000;
constexpr int D      = 64;
constexpr int NE     = 1250000;
constexpr int SB     = (NNODES + 1023) / 1024;  // 98 scan blocks
constexpr int GEMM_BLOCKS = (NNODES + 127) / 128;  // 782
constexpr int HIST_BLOCKS = 1024;

// ---------------------------------------------------------------------------
// Device scratch
// ---------------------------------------------------------------------------
__device__ float  g_h[NNODES * D];
__device__ float  g_x[NNODES * D];
__device__ float  g_dis[NNODES];
__device__ int    g_cnt[NNODES];
__device__ int    g_rowptr[NNODES + 1];
__device__ int    g_cursor[NNODES];
__device__ int    g_colidx[NE];
__device__ int    g_blocksum[SB];
__device__ int    g_blockoff[SB];
__device__ double g_sum[D];
__device__ double g_sumsq[D];
__device__ float  g_scale[D];
__device__ float  g_shift[D];
__device__ int    g_is64;

// ---------------------------------------------------------------------------
// 0. init: zero counters/BN accums; block 0 also detects edge dtype
// ---------------------------------------------------------------------------
__global__ void k_init(const int* __restrict__ e) {
    int i = blockIdx.x * blockDim.x + threadIdx.x;
    if (i < NNODES) g_cnt[i] = 0;
    if (i < D) { g_sum[i] = 0.0; g_sumsq[i] = 0.0; }
    if (blockIdx.x == 0) {
        __shared__ int s_nz;
        if (threadIdx.x == 0) s_nz = 0;
        __syncthreads();
        int nz = 0;
        for (int j = threadIdx.x; j < 2048; j += blockDim.x)
            nz |= (e[2 * j + 1] != 0);
        if (nz) atomicOr(&s_nz, 1);
        __syncthreads();
        if (threadIdx.x == 0) g_is64 = (s_nz == 0) ? 1 : 0;
    }
}

// ---------------------------------------------------------------------------
// GEMM body (round-2 scalar FFMA version): g_h[n] = [dis[n] *] (X[n] @ W^T)
// ---------------------------------------------------------------------------
template <bool SCALE>
__device__ __forceinline__ void gemm_body(const float* __restrict__ X,
                                          const float* __restrict__ W,
                                          int bid) {
    __shared__ float sx[128 * 64];
    __shared__ float sw[64 * 64];    // sw[k*64+d] = W[d][k]
    int tid = threadIdx.x;

    for (int i = tid; i < 4096; i += 256) {
        int d = i >> 6, k = i & 63;
        sw[k * 64 + d] = W[i];
    }
    int n0 = bid * 128;
    const float4* X4 = (const float4*)X;
    float4* sx4 = (float4*)sx;
    for (int i = tid; i < 2048; i += 256) {
        int n = n0 + (i >> 4);
        sx4[i] = (n < NNODES) ? X4[(size_t)n * 16 + (i & 15)]
                              : make_float4(0.f, 0.f, 0.f, 0.f);
    }
    __syncthreads();

    int tc = tid & 7, tr = tid >> 3;
    int d0 = tc * 8;
    int nb = tr * 4;
    float acc[4][8];
#pragma unroll
    for (int i = 0; i < 4; i++)
#pragma unroll
        for (int j = 0; j < 8; j++) acc[i][j] = 0.f;

#pragma unroll 8
    for (int k = 0; k < 64; k++) {
        float4 wa = *(const float4*)&sw[k * 64 + d0];
        float4 wb = *(const float4*)&sw[k * 64 + d0 + 4];
#pragma unroll
        for (int i = 0; i < 4; i++) {
            float xv = sx[(nb + i) * 64 + k];
            acc[i][0] += xv * wa.x; acc[i][1] += xv * wa.y;
            acc[i][2] += xv * wa.z; acc[i][3] += xv * wa.w;
            acc[i][4] += xv * wb.x; acc[i][5] += xv * wb.y;
            acc[i][6] += xv * wb.z; acc[i][7] += xv * wb.w;
        }
    }
#pragma unroll
    for (int i = 0; i < 4; i++) {
        int n = n0 + nb + i;
        if (n < NNODES) {
            float dv = SCALE ? g_dis[n] : 1.0f;
            float4 o0 = make_float4(acc[i][0] * dv, acc[i][1] * dv,
                                    acc[i][2] * dv, acc[i][3] * dv);
            float4 o1 = make_float4(acc[i][4] * dv, acc[i][5] * dv,
                                    acc[i][6] * dv, acc[i][7] * dv);
            *(float4*)&g_h[(size_t)n * 64 + d0]     = o0;
            *(float4*)&g_h[(size_t)n * 64 + d0 + 4] = o1;
        }
    }
}

__device__ __forceinline__ void hist_body(const void* __restrict__ ep, int hb) {
    int i0 = hb * 256 + threadIdx.x;
    int stride = HIST_BLOCKS * 256;
    if (g_is64) {
        const long long* e = (const long long*)ep;
        for (int i = i0; i < NE; i += stride)
            atomicAdd(&g_cnt[(int)e[NE + i]], 1);
    } else {
        const int* e = (const int*)ep;
        for (int i = i0; i < NE; i += stride)
            atomicAdd(&g_cnt[e[NE + i]], 1);
    }
}

// fused: layer-1 GEMM (no dis scaling) || dst histogram
__global__ void __launch_bounds__(256) k_fused1(const float* __restrict__ X,
                                                 const float* __restrict__ W,
                                                 const void* __restrict__ ep) {
    if (blockIdx.x < GEMM_BLOCKS) gemm_body<false>(X, W, blockIdx.x);
    else                          hist_body(ep, blockIdx.x - GEMM_BLOCKS);
}

__global__ void __launch_bounds__(256) k_gemm_s(const float* __restrict__ W) {
    gemm_body<true>(g_x, W, blockIdx.x);
}

// ---------------------------------------------------------------------------
// Parallel scan (3 kernels)
// ---------------------------------------------------------------------------
__global__ void __launch_bounds__(256) k_scan1() {
    __shared__ int warpsum[8];
    int b = blockIdx.x, t = threadIdx.x;
    int base = b * 1024 + t * 4;
    int c[4]; int s = 0;
#pragma unroll
    for (int i = 0; i < 4; i++) {
        int idx = base + i;
        c[i] = (idx < NNODES) ? g_cnt[idx] : 0;
        s += c[i];
    }
    int lane = t & 31, w = t >> 5;
    int v = s;
#pragma unroll
    for (int off = 1; off < 32; off <<= 1) {
        int u = __shfl_up_sync(~0u, v, off);
        if (lane >= off) v += u;
    }
    if (lane == 31) warpsum[w] = v;
    __syncthreads();
    if (t < 8) {
        int u = warpsum[t];
#pragma unroll
        for (int off = 1; off < 8; off <<= 1) {
            int uu = __shfl_up_sync(0xffu, u, off);
            if (t >= off) u += uu;
        }
        warpsum[t] = u;
    }
    __syncthreads();
    int run = v - s + (w > 0 ? warpsum[w - 1] : 0);
#pragma unroll
    for (int i = 0; i < 4; i++) {
        int idx = base + i;
        if (idx < NNODES) g_rowptr[idx] = run;
        run += c[i];
    }
    if (t == 255) g_blocksum[b] = warpsum[7];
}

__global__ void __launch_bounds__(128) k_scan2() {
    __shared__ int sm[128];
    int t = threadIdx.x;
    int v = (t < SB) ? g_blocksum[t] : 0;
    sm[t] = v;
    __syncthreads();
    for (int off = 1; off < 128; off <<= 1) {
        int u = (t >= off) ? sm[t - off] : 0;
        __syncthreads();
        sm[t] += u;
        __syncthreads();
    }
    if (t < SB) g_blockoff[t] = sm[t] - v;
    if (t == SB - 1) g_rowptr[NNODES] = sm[t];
}

__global__ void __launch_bounds__(256) k_scan3() {
    int b = blockIdx.x, t = threadIdx.x;
    int off = g_blockoff[b];
    int base = b * 1024 + t * 4;
#pragma unroll
    for (int i = 0; i < 4; i++) {
        int idx = base + i;
        if (idx < NNODES) {
            int r = g_rowptr[idx] + off;
            g_rowptr[idx] = r;
            g_cursor[idx] = r;
            g_dis[idx] = rsqrtf((float)(g_cnt[idx] + 1));
        }
    }
}

// ---------------------------------------------------------------------------
// CSR fill
// ---------------------------------------------------------------------------
__global__ void k_fill(const void* __restrict__ ep) {
    int i0 = blockIdx.x * blockDim.x + threadIdx.x;
    int stride = gridDim.x * blockDim.x;
    if (g_is64) {
        const long long* e = (const long long*)ep;
        for (int i = i0; i < NE; i += stride) {
            int src = (int)e[i];
            int dst = (int)e[NE + i];
            int p = atomicAdd(&g_cursor[dst], 1);
            g_colidx[p] = src;
        }
    } else {
        const int* e = (const int*)ep;
        for (int i = i0; i < NE; i += stride) {
            int src = e[i];
            int dst = e[NE + i];
            int p = atomicAdd(&g_cursor[dst], 1);
            g_colidx[p] = src;
        }
    }
}

// ---------------------------------------------------------------------------
// Aggregation: warp per node. SRCSCALE: h unscaled -> apply dis[src], dis[n].
// ---------------------------------------------------------------------------
template <bool SRCSCALE>
__global__ void __launch_bounds__(256) k_agg(const float* __restrict__ b) {
    int w = (blockIdx.x * blockDim.x + threadIdx.x) >> 5;
    int l = threadIdx.x & 31;
    if (w >= NNODES) return;
    const float2* __restrict__ h2 = (const float2*)g_h;
    float dvw = g_dis[w];
    float2 acc = h2[(size_t)w * 32 + l];
    if (SRCSCALE) { acc.x *= dvw; acc.y *= dvw; }
    int beg = g_rowptr[w];
    int end = g_rowptr[w + 1];
    int j = beg;
    for (; j + 3 < end; j += 4) {
        int s0 = g_colidx[j],     s1 = g_colidx[j + 1];
        int s2 = g_colidx[j + 2], s3 = g_colidx[j + 3];
        float2 a0 = h2[(size_t)s0 * 32 + l];
        float2 a1 = h2[(size_t)s1 * 32 + l];
        float2 a2 = h2[(size_t)s2 * 32 + l];
        float2 a3 = h2[(size_t)s3 * 32 + l];
        if (SRCSCALE) {
            float d0 = g_dis[s0], d1 = g_dis[s1], d2 = g_dis[s2], d3 = g_dis[s3];
            acc.x += a0.x * d0 + a1.x * d1 + a2.x * d2 + a3.x * d3;
            acc.y += a0.y * d0 + a1.y * d1 + a2.y * d2 + a3.y * d3;
        } else {
            acc.x += (a0.x + a1.x) + (a2.x + a3.x);
            acc.y += (a0.y + a1.y) + (a2.y + a3.y);
        }
    }
    for (; j < end; j++) {
        int s = g_colidx[j];
        float2 a = h2[(size_t)s * 32 + l];
        if (SRCSCALE) {
            float ds = g_dis[s];
            acc.x += a.x * ds; acc.y += a.y * ds;
        } else {
            acc.x += a.x; acc.y += a.y;
        }
    }
    float2 bv = ((const float2*)b)[l];
    float2 r;
    r.x = acc.x * dvw + bv.x;
    r.y = acc.y * dvw + bv.y;
    ((float2*)g_x)[(size_t)w * 32 + l] = r;
}

// ---------------------------------------------------------------------------
// BN column reduction (fp32 inner, double only at block/global reduce)
// ---------------------------------------------------------------------------
__global__ void __launch_bounds__(256) k_bnred() {
    int d  = threadIdx.x & 63;
    int r0 = blockIdx.x * 4 + (threadIdx.x >> 6);
    int rs = gridDim.x * 4;
    float s = 0.f, q = 0.f;
    for (int n = r0; n < NNODES; n += rs) {
        float v = g_x[(size_t)n * 64 + d];
        s += v;
        q += v * v;
    }
    __shared__ double ss[256], sq[256];
    ss[threadIdx.x] = (double)s;
    sq[threadIdx.x] = (double)q;
    __syncthreads();
    if (threadIdx.x < 64) {
        double sd = ss[threadIdx.x] + ss[threadIdx.x + 64] + ss[threadIdx.x + 128] + ss[threadIdx.x + 192];
        double qd = sq[threadIdx.x] + sq[threadIdx.x + 64] + sq[threadIdx.x + 128] + sq[threadIdx.x + 192];
        atomicAdd(&g_sum[d], sd);
        atomicAdd(&g_sumsq[d], qd);
    }
}

__global__ void k_bnprep(const float* __restrict__ gamma,
                         const float* __restrict__ beta) {
    int d = threadIdx.x;
    if (d >= D) return;
    double mean = g_sum[d] / (double)NNODES;
    double var  = g_sumsq[d] / (double)NNODES - mean * mean;
    double inv  = 1.0 / sqrt(var + 1e-5);
    double sc   = (double)gamma[d] * inv;
    g_scale[d] = (float)sc;
    g_shift[d] = (float)((double)beta[d] - mean * sc);
}

__global__ void __launch_bounds__(256) k_fin(float* __restrict__ out) {
    int i = blockIdx.x * blockDim.x + threadIdx.x;
    if (i >= NNODES * 16) return;
    float4 v = ((const float4*)g_x)[i];
    int d = (i & 15) * 4;
    v.x = v.x * g_scale[d + 0] + g_shift[d + 0];
    v.y = v.y * g_scale[d + 1] + g_shift[d + 1];
    v.z = v.z * g_scale[d + 2] + g_shift[d + 2];
    v.w = v.w * g_scale[d + 3] + g_shift[d + 3];
    ((float4*)out)[i] = v;
}

// ---------------------------------------------------------------------------
// Launch
// ---------------------------------------------------------------------------
extern "C" void kernel_launch(void* const* d_in, const int* in_sizes, int n_in,
                              void* d_out, int out_size) {
    const float* x     = (const float*)d_in[0];
    const void*  ei    = d_in[1];
    const float* Ws    = (const float*)d_in[2];
    const float* bs    = (const float*)d_in[3];
    const float* gamma = (const float*)d_in[4];
    const float* beta  = (const float*)d_in[5];
    float* out = (float*)d_out;

    int agg_blocks = (NNODES * 32 + 255) / 256;

    k_init<<<(NNODES + 255) / 256, 256>>>((const int*)ei);
    k_fused1<<<GEMM_BLOCKS + HIST_BLOCKS, 256>>>(x, Ws, ei);
    k_scan1<<<SB, 256>>>();
    k_scan2<<<1, 128>>>();
    k_scan3<<<SB, 256>>>();
    k_fill<<<2048, 256>>>(ei);

    k_agg<true><<<agg_blocks, 256>>>(bs);  // layer 1: dis applied per edge

    k_gemm_s<<<GEMM_BLOCKS, 256>>>(Ws + 1 * 64 * 64);
    k_agg<false><<<agg_blocks, 256>>>(bs + 1 * 64);

    k_gemm_s<<<GEMM_BLOCKS, 256>>>(Ws + 2 * 64 * 64);
    k_agg<false><<<agg_blocks, 256>>>(bs + 2 * 64);

    k_bnred<<<512, 256>>>();
    k_bnprep<<<1, 64>>>(gamma, beta);
    k_fin<<<(NNODES * 16 + 255) / 256, 256>>>(out);
}